// round 15
// baseline (speedup 1.0000x reference)
#include <cuda_runtime.h>
#include <cstdint>

// ---------------------------------------------------------------------------
// MoE MLP, routed (top-k) formulation on legacy mma.sync tf32 HMMA
// (tcgen05 unavailable: harness compiles via non-'a' compute_103 PTX).
//
//   route:  per-expert compact token lists from probs>0 (TOPK=2 of E=4)
//   GEMM1:  a_e = gelu( X[list_e] @ W1[e] ) * probs[list_e,e]   (tf32-rounded)
//   GEMM2:  y_e = a_e @ W2[e]
//   combine: out[t] = resid[t] + sum_{e in topk(t)} y_e[slot(t,e)]
//
// R15: expert-staggered GEMM overlap. k1/k2 individually sit at ~58% tensor
// (latency-bound); their only dependency is per-expert. One MIXED kernel runs
// MODE0 CTAs for expert e and MODE1 CTAs for expert e-1 in the same grid:
//   L0: k1(e0) | L1: k1(e1)+k2(e0) | L2: k1(e2)+k2(e1) | L3: k1(e3)+k2(e2)
//   L4: k2(e3) | combine
// Launch boundaries provide the k1(e)->k2(e) ordering; heterogeneous CTAs on
// one SM fill each other's bubbles; k2's A-slab is L2-hot. Mainloop = frozen
// R13 optimum (64x128, 2x2 warps of 32x64, BK=32, 3-stage, occ 3).
// ---------------------------------------------------------------------------

static constexpr int T_TOK = 2048;   // S*B
static constexpr int HID   = 1024;   // H
static constexpr int FFN   = 4096;   // F
static constexpr int NEXP  = 4;      // E
static constexpr int EF    = NEXP * FFN;  // 16384

static constexpr int CAP  = 2112;    // per-expert row capacity (64*33)
static constexpr int TPE  = 33;      // m-tiles per expert (CAP/64)
static constexpr int N1   = (FFN / 128) * TPE;   // 1056 MODE0 CTAs per expert
static constexpr int N2   = (HID / 128) * TPE;   // 264  MODE1 CTAs per expert

// static device scratch (no allocation allowed)
__device__ float g_xr  [(size_t)T_TOK * HID];      //   8 MB rounded X
__device__ float g_w1t [(size_t)EF * HID];         //  67 MB W1^T [e*F+f][h]
__device__ float g_w2t [(size_t)HID * EF];         //  67 MB W2^T [h][e*F+f]
__device__ float g_c1p [(size_t)NEXP * CAP * FFN]; // 138 MB compact act
__device__ float g_y   [(size_t)NEXP * CAP * HID]; //  35 MB compact y
__device__ int   g_idx [NEXP * CAP];               // expert -> token list (always valid ids)
__device__ int   g_slot[T_TOK * NEXP];             // (t,e) -> slot
__device__ int   g_cnt [NEXP];                     // zero at launch entry (reset by combine)

// ---------------------------------------------------------------------------
// helpers
// ---------------------------------------------------------------------------
__device__ __forceinline__ uint32_t smem_u32(const void* p) {
    uint32_t a;
    asm("{ .reg .u64 t; cvta.to.shared.u64 t, %1; cvt.u32.u64 %0, t; }"
        : "=r"(a) : "l"(p));
    return a;
}

__device__ __forceinline__ float to_tf32(float x) {
    uint32_t u;
    asm("cvt.rna.tf32.f32 %0, %1;" : "=r"(u) : "f"(x));
    return __uint_as_float(u);
}

__device__ __forceinline__ uint32_t sw128(uint32_t off) {
    return off ^ ((off >> 3) & 0x70);
}

__device__ __forceinline__ void cpa16(uint32_t dst, const void* src) {
    asm volatile("cp.async.cg.shared.global [%0], [%1], 16;"
                 :: "r"(dst), "l"(src) : "memory");
}

__device__ __forceinline__ void ldsm4(uint32_t* d, uint32_t addr) {
    asm volatile("ldmatrix.sync.aligned.m8n8.x4.shared.b16 {%0,%1,%2,%3}, [%4];"
                 : "=r"(d[0]), "=r"(d[1]), "=r"(d[2]), "=r"(d[3]) : "r"(addr));
}

__device__ __forceinline__ void mma8(float* c, const uint32_t* a,
                                     uint32_t b0, uint32_t b1) {
    asm volatile(
        "mma.sync.aligned.m16n8k8.row.col.f32.tf32.tf32.f32 "
        "{%0,%1,%2,%3}, {%4,%5,%6,%7}, {%8,%9}, {%0,%1,%2,%3};"
        : "+f"(c[0]), "+f"(c[1]), "+f"(c[2]), "+f"(c[3])
        : "r"(a[0]), "r"(a[1]), "r"(a[2]), "r"(a[3]), "r"(b0), "r"(b1));
}

__device__ __forceinline__ float gelu_exact(float x) {
    return 0.5f * x * (1.0f + erff(x * 0.70710678118654752f));
}

// ---------------------------------------------------------------------------
// merged operand prep + routing: one launch, independent jobs overlap.
// ---------------------------------------------------------------------------
__device__ __forceinline__ void tr_tile(const float* __restrict__ in,
                                        float* __restrict__ out,
                                        int R, int C, int bx, int by, int bz,
                                        float (*tile)[68], int tid) {
    size_t base = (size_t)bz * R * C;
    int c0 = bx << 6, r0 = by << 6;
    int tx = tid & 15, ty = tid >> 4;              // 16 x 16
    #pragma unroll
    for (int i = 0; i < 4; i++) {
        int rr = ty + (i << 4);
        float4 v = *(const float4*)&in[base + (size_t)(r0 + rr) * C + c0 + (tx << 2)];
        tile[(tx << 2) + 0][rr] = to_tf32(v.x);
        tile[(tx << 2) + 1][rr] = to_tf32(v.y);
        tile[(tx << 2) + 2][rr] = to_tf32(v.z);
        tile[(tx << 2) + 3][rr] = to_tf32(v.w);
    }
    __syncthreads();
    #pragma unroll
    for (int i = 0; i < 4; i++) {
        int cc = ty + (i << 4);
        float4 w = *(const float4*)&tile[cc][tx << 2];
        *(float4*)&out[base + (size_t)(c0 + cc) * R + r0 + (tx << 2)] = w;
    }
}

__global__ void prep(const float* __restrict__ w1, float* __restrict__ w1t,
                     const float* __restrict__ w2, float* __restrict__ w2t,
                     const float* __restrict__ x,  float* __restrict__ xr,
                     const float* __restrict__ probs,
                     int* idx, int* slot, int* cnt) {
    __shared__ float tile[64][68];
    const int b   = blockIdx.x;
    const int tid = threadIdx.x;
    if (b < 4096) {                               // W1 transpose (per expert)
        int e   = b >> 10;
        int rem = b & 1023;
        tr_tile(w1, w1t, HID, FFN, rem & 63, rem >> 6, e, tile, tid);
    } else if (b < 8192) {                        // W2 transpose
        int rem = b - 4096;
        tr_tile(w2, w2t, EF, HID, rem & 15, rem >> 4, 0, tile, tid);
    } else if (b < 10240) {                       // X rounding
        int i = (b - 8192) * 256 + tid;
        float4 v = ((const float4*)x)[i];
        v.x = to_tf32(v.x); v.y = to_tf32(v.y);
        v.z = to_tf32(v.z); v.w = to_tf32(v.w);
        ((float4*)xr)[i] = v;
    } else {                                      // routing build
        int t = (b - 10240) * 256 + tid;
        if (t < T_TOK) {
            #pragma unroll
            for (int e = 0; e < NEXP; e++) {
                if (probs[t * NEXP + e] > 0.0f) {
                    int pos = atomicAdd(&cnt[e], 1);
                    idx[e * CAP + pos] = t;
                    slot[t * NEXP + e] = pos;
                }
            }
        }
    }
}

// combine: out[t] = resid[t] + sum_e (probs>0) y[e][slot];
// block 0 also resets cnt so the next replay starts clean.
__global__ void combine(const float* __restrict__ y,
                        const float* __restrict__ probs,
                        const int* __restrict__ slot,
                        const float* __restrict__ resid,
                        float* __restrict__ out,
                        int* cnt) {
    int t = blockIdx.x;
    int j = threadIdx.x;
    if (t == 0 && j < NEXP) cnt[j] = 0;
    float4 acc = ((const float4*)resid)[t * (HID / 4) + j];
    #pragma unroll
    for (int e = 0; e < NEXP; e++) {
        if (probs[t * NEXP + e] > 0.0f) {
            int s = slot[t * NEXP + e];
            float4 v = ((const float4*)y)[((size_t)e * CAP + s) * (HID / 4) + j];
            acc.x += v.x; acc.y += v.y; acc.z += v.z; acc.w += v.w;
        }
    }
    ((float4*)out)[t * (HID / 4) + j] = acc;
}

// ---------------------------------------------------------------------------
// GEMM body (R13 frozen optimum) as a device function.
// CTA tile 64x128, warp grid 2x2 (32x64 warp tile), BK=32, 3-stage cp.async,
// one barrier per chunk (wait_group 1, always-commit).
// MODE 0 (fc1): A rows gathered via token list; epi gelu*probs -> c1p (tf32).
// MODE 1 (fc2): A compact rows; epi plain store -> y.
// ---------------------------------------------------------------------------
template<int MODE>
__device__ __forceinline__ void gemm_body(
    int e, int tile, int n0,
    const float* __restrict__ A, const float* __restrict__ Bt,
    const float* __restrict__ probs,
    const int* __restrict__ idx, const int* __restrict__ cnt,
    float* __restrict__ Cout, int K, char* smem)
{
    constexpr int BMT     = 64;
    constexpr int BNT     = 128;
    constexpr int THREADS = 128;
    constexpr int STAGES  = 3;
    constexpr int WM      = 32;
    constexpr int MT      = 2;
    constexpr int NT      = 8;
    constexpr int A_BYTES = BMT * 128;
    constexpr int B_BYTES = BNT * 128;
    constexpr int STAGE   = A_BYTES + B_BYTES;

    const uint32_t sb = smem_u32(smem);
    int* s_token = (int*)(smem + STAGES * STAGE);

    if (tile * BMT >= cnt[e]) return;

    const int tid  = threadIdx.x;
    const int wid  = tid >> 5;
    const int lane = tid & 31;
    const int wm   = wid >> 1;
    const int wn   = wid & 1;
    const int row_base = e * CAP + tile * BMT;

    if (MODE == 0) {
        if (tid < BMT) s_token[tid] = idx[row_base + tid];
    }
    __syncthreads();

    const int CCH = K / 32;

    auto issue = [&](int c, int s) {
        uint32_t dA = sb + (uint32_t)s * STAGE;
        uint32_t dB = dA + A_BYTES;
        const int k0 = c * 32;
        #pragma unroll
        for (int i = 0; i < BMT * 8 / THREADS; i++) {   // A: 64 rows x 2 x 16B
            int id2 = tid + i * THREADS;
            int row = id2 >> 3, cb = (id2 & 7) << 4;
            const float* asrc;
            if (MODE == 0)
                asrc = A + (size_t)s_token[row] * K + k0 + (cb >> 2);
            else
                asrc = A + (size_t)(row_base + row) * K + k0 + (cb >> 2);
            cpa16(dA + sw128((uint32_t)(row * 128 + cb)), asrc);
        }
        #pragma unroll
        for (int i = 0; i < BNT * 8 / THREADS; i++) {   // B: 128 rows K-contig
            int id2 = tid + i * THREADS;
            int row = id2 >> 3, cb = (id2 & 7) << 4;
            const float* bsrc;
            if (MODE == 0)   // w1t rows e*F + n, stride K (=HID)
                bsrc = Bt + (size_t)(e * FFN + n0 + row) * K + k0 + (cb >> 2);
            else             // w2t rows n (stride EF), expert cols e*F + k
                bsrc = Bt + (size_t)(n0 + row) * EF + e * FFN + k0 + (cb >> 2);
            cpa16(dB + sw128((uint32_t)(row * 128 + cb)), bsrc);
        }
    };

    #pragma unroll
    for (int s = 0; s < STAGES - 1; s++) {
        issue(s, s);
        asm volatile("cp.async.commit_group;" ::: "memory");
    }

    float acc[MT][NT][4];
    #pragma unroll
    for (int mt = 0; mt < MT; mt++)
        #pragma unroll
        for (int nt = 0; nt < NT; nt++)
            #pragma unroll
            for (int i = 0; i < 4; i++) acc[mt][nt][i] = 0.0f;

    const int g = lane >> 3, r = lane & 7;

    #pragma unroll 1
    for (int c = 0; c < CCH; c++) {
        asm volatile("cp.async.wait_group 1;" ::: "memory");
        __syncthreads();
        if (c + STAGES - 1 < CCH) issue(c + STAGES - 1, (c + STAGES - 1) % STAGES);
        asm volatile("cp.async.commit_group;" ::: "memory");

        const uint32_t sA  = sb + (uint32_t)(c % STAGES) * STAGE;
        const uint32_t sBm = sA + A_BYTES;

        #pragma unroll
        for (int ks = 0; ks < 4; ks++) {
            uint32_t bf[NT * 2];
            #pragma unroll
            for (int p = 0; p < NT / 2; p++) {
                int brow = wn * 64 + p * 16 + ((g >> 1) << 3) + r;
                int bcol = ks * 32 + ((g & 1) << 4);
                ldsm4(&bf[4 * p], sBm + sw128((uint32_t)(brow * 128 + bcol)));
            }
            uint32_t af[2][4];
            {
                int arow = wm * WM + ((g & 1) << 3) + r;
                int acol = ks * 32 + ((g >> 1) << 4);
                ldsm4(af[0], sA + sw128((uint32_t)(arow * 128 + acol)));
            }
            #pragma unroll
            for (int mt = 0; mt < MT; mt++) {
                if (mt + 1 < MT) {
                    int arow = wm * WM + (mt + 1) * 16 + ((g & 1) << 3) + r;
                    int acol = ks * 32 + ((g >> 1) << 4);
                    ldsm4(af[(mt + 1) & 1], sA + sw128((uint32_t)(arow * 128 + acol)));
                }
                #pragma unroll
                for (int nt = 0; nt < NT; nt++)
                    mma8(acc[mt][nt], af[mt & 1], bf[nt * 2], bf[nt * 2 + 1]);
            }
        }
    }

    const int qr = lane >> 2, rm = lane & 3;
    const int ldc = (MODE == 0) ? FFN : HID;

    #pragma unroll
    for (int mt = 0; mt < MT; mt++) {
        const int lr0 = wm * WM + mt * 16 + qr;
        const int lr1 = lr0 + 8;
        float p0 = 1.0f, p1 = 1.0f;
        if (MODE == 0) {
            p0 = probs[s_token[lr0] * NEXP + e];
            p1 = probs[s_token[lr1] * NEXP + e];
        }
        #pragma unroll
        for (int nt = 0; nt < NT; nt++) {
            const int col = n0 + wn * 64 + nt * 8 + (rm << 1);
            float2 v0, v1;
            if (MODE == 0) {
                v0.x = to_tf32(gelu_exact(acc[mt][nt][0]) * p0);
                v0.y = to_tf32(gelu_exact(acc[mt][nt][1]) * p0);
                v1.x = to_tf32(gelu_exact(acc[mt][nt][2]) * p1);
                v1.y = to_tf32(gelu_exact(acc[mt][nt][3]) * p1);
            } else {
                v0.x = acc[mt][nt][0]; v0.y = acc[mt][nt][1];
                v1.x = acc[mt][nt][2]; v1.y = acc[mt][nt][3];
            }
            *(float2*)&Cout[(size_t)(row_base + lr0) * ldc + col] = v0;
            *(float2*)&Cout[(size_t)(row_base + lr1) * ldc + col] = v1;
        }
    }
}

// ---------------------------------------------------------------------------
// Mixed kernel: blocks [0, n1) run MODE0 (fc1) for expert k1_e; blocks
// [n1, n1+n2) run MODE1 (fc2) for expert k2_e. Launch boundaries order
// k1(e) before k2(e); within a launch the two modes share SMs and fill
// each other's latency bubbles.
// ---------------------------------------------------------------------------
__global__ void __launch_bounds__(128, 3)
moe_mixed(int k1_e, int n1, int k2_e,
          const float* __restrict__ xr,  const float* __restrict__ w1t,
          const float* __restrict__ w2t, const float* __restrict__ probs,
          const int* __restrict__ idx,   const int* __restrict__ cnt,
          float* __restrict__ c1p,       float* __restrict__ y)
{
    extern __shared__ __align__(128) char smem[];
    const int b = blockIdx.x;
    if (b < n1) {
        // MODE0: mtile fastest (adjacent CTAs share the w1t B slab in L2)
        int tile = b % TPE;
        int n0   = (b / TPE) * 128;
        gemm_body<0>(k1_e, tile, n0, xr, w1t, probs, idx, cnt, c1p, HID, smem);
    } else {
        // MODE1: nb fastest (adjacent CTAs share the c1p A panel in L2)
        int b2   = b - n1;
        int n0   = (b2 & 7) * 128;
        int tile = b2 >> 3;
        gemm_body<1>(k2_e, tile, n0, c1p, w2t, probs, idx, cnt, y, FFN, smem);
    }
}

// ---------------------------------------------------------------------------
// launch
// ---------------------------------------------------------------------------
extern "C" void kernel_launch(void* const* d_in, const int* in_sizes, int n_in,
                              void* d_out, int out_size) {
    const float* x     = (const float*)d_in[0];   // hidden_states [T,H]
    const float* resid = (const float*)d_in[1];   // mlp_residual  [T,H]
    const float* probs = (const float*)d_in[2];   // probs [T,E] (masked)
    // d_in[3] = routing_map (unused: probs>0 is the same mask, dtype-safe)
    const float* w1    = (const float*)d_in[4];   // [E,H,F]
    const float* w2    = (const float*)d_in[5];   // [E,F,H]
    float* out = (float*)d_out;

    float *xr, *w1t, *w2t, *c1p, *yp;
    int *idxp, *slotp, *cntp;
    cudaGetSymbolAddress((void**)&xr,   g_xr);
    cudaGetSymbolAddress((void**)&w1t,  g_w1t);
    cudaGetSymbolAddress((void**)&w2t,  g_w2t);
    cudaGetSymbolAddress((void**)&c1p,  g_c1p);
    cudaGetSymbolAddress((void**)&yp,   g_y);
    cudaGetSymbolAddress((void**)&idxp, g_idx);
    cudaGetSymbolAddress((void**)&slotp, g_slot);
    cudaGetSymbolAddress((void**)&cntp, g_cnt);

    // 64x128 CTA, 3-stage, occ 3: smem = 3*24576 + 256 = 73984 (x3 <= 228KB)
    constexpr int SMEM = 3 * (64 * 128 + 128 * 128) + 64 * 4;
    cudaFuncSetAttribute(moe_mixed, cudaFuncAttributeMaxDynamicSharedMemorySize,
                         SMEM);

    // merged prep + routing (cnt==0 at entry: static init / reset by combine)
    prep<<<10248, 256>>>(w1, w1t, w2, w2t, x, xr, probs, idxp, slotp, cntp);

    // expert-staggered pipeline: k1(e) and k2(e-1) share each launch
    moe_mixed<<<N1,      128, SMEM>>>(0, N1, -1, xr, w1t, w2t, probs, idxp, cntp, c1p, yp);
    moe_mixed<<<N1 + N2, 128, SMEM>>>(1, N1,  0, xr, w1t, w2t, probs, idxp, cntp, c1p, yp);
    moe_mixed<<<N1 + N2, 128, SMEM>>>(2, N1,  1, xr, w1t, w2t, probs, idxp, cntp, c1p, yp);
    moe_mixed<<<N1 + N2, 128, SMEM>>>(3, N1,  2, xr, w1t, w2t, probs, idxp, cntp, c1p, yp);
    moe_mixed<<<N2,      128, SMEM>>>(-1, 0,  3, xr, w1t, w2t, probs, idxp, cntp, c1p, yp);

    // combine: out = resid + sum_topk y; also resets cnt for next replay
    combine<<<T_TOK, 256>>>(yp, probs, slotp, resid, out, cntp);
}

// round 16
// speedup vs baseline: 2.2557x; 2.2557x over previous
#include <cuda_runtime.h>
#include <cuda_fp16.h>
#include <cstdint>

// ---------------------------------------------------------------------------
// MoE MLP, routed (top-k) formulation on mma.sync m16n8k16 FP16 HMMA
// (tcgen05 unavailable: harness compiles via non-'a' compute_103 PTX).
//
//   route:  per-expert compact token lists from probs>0 (TOPK=2 of E=4)
//   GEMM1:  a_e = gelu( X[list_e] @ W1[e] ) * probs[list_e,e]  (fp16-rounded)
//   GEMM2:  y_e = a_e @ W2[e]                                  (fp32 out)
//   combine: out[t] = resid[t] + sum_{e in topk(t)} y_e[slot(t,e)]
//
// R16: R15 mixing reverted (regression). Precision pivot: fp16 has the SAME
// 10-bit mantissa as tf32 -> switch both GEMMs to m16n8k16.f16 (fp32 accum).
// Per 128-byte smem row K coverage doubles (32->64): MMA count, LDSM
// wavefronts, cp.async bytes and BARRIER count all halve -- the barrier/
// latency bubble is the measured binding constraint. Byte-level smem
// addressing (SW128 + ldmatrix tiles) is identical to the tf32-as-b16 path.
// Tile config frozen at R13 optimum: 64x128 CTA, 2x2 warps of 32x64, 3-stage,
// occ 3.
// ---------------------------------------------------------------------------

static constexpr int T_TOK = 2048;   // S*B
static constexpr int HID   = 1024;   // H
static constexpr int FFN   = 4096;   // F
static constexpr int NEXP  = 4;      // E
static constexpr int EF    = NEXP * FFN;  // 16384

static constexpr int CAP  = 2112;    // per-expert row capacity (64*33)
static constexpr int TPE  = 33;      // m-tiles per expert (CAP/64)

// static device scratch (no allocation allowed)
__device__ __half g_xr  [(size_t)T_TOK * HID];      //   4 MB rounded X (fp16)
__device__ __half g_w1t [(size_t)EF * HID];         //  34 MB W1^T [e*F+f][h]
__device__ __half g_w2t [(size_t)HID * EF];         //  34 MB W2^T [h][e*F+f]
__device__ __half g_c1p [(size_t)NEXP * CAP * FFN]; //  69 MB compact act
__device__ float  g_y   [(size_t)NEXP * CAP * HID]; //  35 MB compact y (fp32)
__device__ int    g_idx [NEXP * CAP];               // expert -> token list (valid ids)
__device__ int    g_slot[T_TOK * NEXP];             // (t,e) -> slot
__device__ int    g_cnt [NEXP];                     // zero at entry (reset by combine)

// ---------------------------------------------------------------------------
// helpers
// ---------------------------------------------------------------------------
__device__ __forceinline__ uint32_t smem_u32(const void* p) {
    uint32_t a;
    asm("{ .reg .u64 t; cvta.to.shared.u64 t, %1; cvt.u32.u64 %0, t; }"
        : "=r"(a) : "l"(p));
    return a;
}

__device__ __forceinline__ uint32_t sw128(uint32_t off) {
    return off ^ ((off >> 3) & 0x70);
}

__device__ __forceinline__ void cpa16(uint32_t dst, const void* src) {
    asm volatile("cp.async.cg.shared.global [%0], [%1], 16;"
                 :: "r"(dst), "l"(src) : "memory");
}

__device__ __forceinline__ void ldsm4(uint32_t* d, uint32_t addr) {
    asm volatile("ldmatrix.sync.aligned.m8n8.x4.shared.b16 {%0,%1,%2,%3}, [%4];"
                 : "=r"(d[0]), "=r"(d[1]), "=r"(d[2]), "=r"(d[3]) : "r"(addr));
}

// fp16 MMA, K=16 per instruction, fp32 accumulate
__device__ __forceinline__ void mma16(float* c, const uint32_t* a,
                                      uint32_t b0, uint32_t b1) {
    asm volatile(
        "mma.sync.aligned.m16n8k16.row.col.f32.f16.f16.f32 "
        "{%0,%1,%2,%3}, {%4,%5,%6,%7}, {%8,%9}, {%0,%1,%2,%3};"
        : "+f"(c[0]), "+f"(c[1]), "+f"(c[2]), "+f"(c[3])
        : "r"(a[0]), "r"(a[1]), "r"(a[2]), "r"(a[3]), "r"(b0), "r"(b1));
}

__device__ __forceinline__ float gelu_exact(float x) {
    return 0.5f * x * (1.0f + erff(x * 0.70710678118654752f));
}

// ---------------------------------------------------------------------------
// merged operand prep + routing: one launch, independent jobs overlap.
//   blocks [0, 4096):      W1 [E,H,F] -> w1t [E*F][H] half (transpose + cvt)
//   blocks [4096, 8192):   W2 [EF,H]  -> w2t [H][EF]  half (transpose + cvt)
//   blocks [8192, 10240):  X -> xr half
//   blocks [10240, 10248): route_build (cnt == 0 at launch entry)
// ---------------------------------------------------------------------------
__device__ __forceinline__ void tr_tile(const float* __restrict__ in,
                                        __half* __restrict__ out,
                                        int R, int C, int bx, int by, int bz,
                                        float (*tile)[68], int tid) {
    size_t base = (size_t)bz * R * C;
    int c0 = bx << 6, r0 = by << 6;
    int tx = tid & 15, ty = tid >> 4;              // 16 x 16
    #pragma unroll
    for (int i = 0; i < 4; i++) {
        int rr = ty + (i << 4);
        float4 v = *(const float4*)&in[base + (size_t)(r0 + rr) * C + c0 + (tx << 2)];
        tile[(tx << 2) + 0][rr] = v.x;
        tile[(tx << 2) + 1][rr] = v.y;
        tile[(tx << 2) + 2][rr] = v.z;
        tile[(tx << 2) + 3][rr] = v.w;
    }
    __syncthreads();
    #pragma unroll
    for (int i = 0; i < 4; i++) {
        int cc = ty + (i << 4);
        float4 w = *(const float4*)&tile[cc][tx << 2];
        __half2 h01 = __floats2half2_rn(w.x, w.y);
        __half2 h23 = __floats2half2_rn(w.z, w.w);
        __half2* dst = (__half2*)&out[base + (size_t)(c0 + cc) * R + r0 + (tx << 2)];
        dst[0] = h01;
        dst[1] = h23;
    }
}

__global__ void prep(const float* __restrict__ w1, __half* __restrict__ w1t,
                     const float* __restrict__ w2, __half* __restrict__ w2t,
                     const float* __restrict__ x,  __half* __restrict__ xr,
                     const float* __restrict__ probs,
                     int* idx, int* slot, int* cnt) {
    __shared__ float tile[64][68];
    const int b   = blockIdx.x;
    const int tid = threadIdx.x;
    if (b < 4096) {                               // W1 transpose (per expert)
        int e   = b >> 10;
        int rem = b & 1023;
        tr_tile(w1, w1t, HID, FFN, rem & 63, rem >> 6, e, tile, tid);
    } else if (b < 8192) {                        // W2 transpose
        int rem = b - 4096;
        tr_tile(w2, w2t, EF, HID, rem & 15, rem >> 4, 0, tile, tid);
    } else if (b < 10240) {                       // X -> fp16
        int i = (b - 8192) * 256 + tid;           // float4 index
        float4 v = ((const float4*)x)[i];
        __half2 h01 = __floats2half2_rn(v.x, v.y);
        __half2 h23 = __floats2half2_rn(v.z, v.w);
        ((__half2*)xr)[i * 2 + 0] = h01;
        ((__half2*)xr)[i * 2 + 1] = h23;
    } else {                                      // routing build
        int t = (b - 10240) * 256 + tid;
        if (t < T_TOK) {
            #pragma unroll
            for (int e = 0; e < NEXP; e++) {
                if (probs[t * NEXP + e] > 0.0f) {
                    int pos = atomicAdd(&cnt[e], 1);
                    idx[e * CAP + pos] = t;
                    slot[t * NEXP + e] = pos;
                }
            }
        }
    }
}

// combine: out[t] = resid[t] + sum_e (probs>0) y[e][slot];
// block 0 also resets cnt so the next replay starts clean.
__global__ void combine(const float* __restrict__ y,
                        const float* __restrict__ probs,
                        const int* __restrict__ slot,
                        const float* __restrict__ resid,
                        float* __restrict__ out,
                        int* cnt) {
    int t = blockIdx.x;
    int j = threadIdx.x;
    if (t == 0 && j < NEXP) cnt[j] = 0;
    float4 acc = ((const float4*)resid)[t * (HID / 4) + j];
    #pragma unroll
    for (int e = 0; e < NEXP; e++) {
        if (probs[t * NEXP + e] > 0.0f) {
            int s = slot[t * NEXP + e];
            float4 v = ((const float4*)y)[((size_t)e * CAP + s) * (HID / 4) + j];
            acc.x += v.x; acc.y += v.y; acc.z += v.z; acc.w += v.w;
        }
    }
    ((float4*)out)[t * (HID / 4) + j] = acc;
}

// ---------------------------------------------------------------------------
// Routed GEMM (fp16 operands). CTA tile 64x128, warp grid 2x2 (32x64 warp
// tile), K-chunk = 64 halves (128-byte rows), 3-stage cp.async, ONE barrier
// per chunk (wait_group 1, always-commit), occupancy 3.
// Grid mapping:
//   MODE 0: blockIdx.x = mtile (fastest), blockIdx.y = e*32 + nb.
//   MODE 1: blockIdx.x = nb (fastest),    blockIdx.y = e*TPE + mtile.
// CTAs past cnt[e] exit. idx entries are always valid token ids.
// MODE 0 (fc1): A=xr gathered via token list; epi gelu*probs -> c1p (fp16).
// MODE 1 (fc2): A=c1p compact rows; epi fp32 store -> y.
// ---------------------------------------------------------------------------
template<int MODE>
__global__ void __launch_bounds__(128, 3)
moe_gemm(const __half* __restrict__ A,    // MODE0: g_xr [T,H]; MODE1: g_c1p
         const __half* __restrict__ Bt,   // MODE0: g_w1t [EF][H]; MODE1: g_w2t [H][EF]
         const float* __restrict__ probs, // [T,E]
         const int* __restrict__ idx,
         const int* __restrict__ cnt,
         __half* __restrict__ CoutH,      // MODE0: g_c1p
         float*  __restrict__ CoutF,      // MODE1: g_y
         int K)                           // in halves: MODE0 HID; MODE1 FFN
{
    constexpr int BMT     = 64;
    constexpr int BNT     = 128;
    constexpr int THREADS = 128;
    constexpr int STAGES  = 3;
    constexpr int WM      = 32;
    constexpr int MT      = 2;
    constexpr int NT      = 8;            // warp tile N = 64
    constexpr int A_BYTES = BMT * 128;    // 8192  (64 rows x 64 halves)
    constexpr int B_BYTES = BNT * 128;    // 16384
    constexpr int STAGE   = A_BYTES + B_BYTES;   // 24576

    extern __shared__ __align__(128) char smem[];
    const uint32_t sb = smem_u32(smem);
    int* s_token = (int*)(smem + STAGES * STAGE);

    int e, tile, n0;
    if (MODE == 0) {
        tile = blockIdx.x;                // mtile fastest: B-slab L2 sharing
        e    = blockIdx.y >> 5;
        n0   = (blockIdx.y & 31) * BNT;
    } else {
        n0   = blockIdx.x * BNT;          // nb fastest: A-panel L2 sharing
        e    = blockIdx.y / TPE;
        tile = blockIdx.y % TPE;
    }
    if (tile * BMT >= cnt[e]) return;

    const int tid  = threadIdx.x;
    const int wid  = tid >> 5;
    const int lane = tid & 31;
    const int wm   = wid >> 1;
    const int wn   = wid & 1;
    const int row_base = e * CAP + tile * BMT;

    if (MODE == 0) {
        if (tid < BMT) s_token[tid] = idx[row_base + tid];
    }
    __syncthreads();

    const int CCH = K / 64;               // 64-half chunks (16 or 64)

    auto issue = [&](int c, int s) {
        uint32_t dA = sb + (uint32_t)s * STAGE;
        uint32_t dB = dA + A_BYTES;
        const int k0 = c * 64;            // halves
        #pragma unroll
        for (int i = 0; i < BMT * 8 / THREADS; i++) {   // A: 64 rows x 8 x 16B
            int id2 = tid + i * THREADS;
            int row = id2 >> 3, cb = (id2 & 7) << 4;    // cb: byte offset in row
            const __half* asrc;
            if (MODE == 0)
                asrc = A + (size_t)s_token[row] * K + k0 + (cb >> 1);
            else
                asrc = A + (size_t)(row_base + row) * K + k0 + (cb >> 1);
            cpa16(dA + sw128((uint32_t)(row * 128 + cb)), asrc);
        }
        #pragma unroll
        for (int i = 0; i < BNT * 8 / THREADS; i++) {   // B: 128 rows K-contig
            int id2 = tid + i * THREADS;
            int row = id2 >> 3, cb = (id2 & 7) << 4;
            const __half* bsrc;
            if (MODE == 0)   // w1t rows e*F + n, stride K (=HID halves)
                bsrc = Bt + (size_t)(e * FFN + n0 + row) * K + k0 + (cb >> 1);
            else             // w2t rows n (stride EF), expert cols e*F + k
                bsrc = Bt + (size_t)(n0 + row) * EF + e * FFN + k0 + (cb >> 1);
            cpa16(dB + sw128((uint32_t)(row * 128 + cb)), bsrc);
        }
    };

    // prologue: stages 0,1
    #pragma unroll
    for (int s = 0; s < STAGES - 1; s++) {
        issue(s, s);
        asm volatile("cp.async.commit_group;" ::: "memory");
    }

    float acc[MT][NT][4];
    #pragma unroll
    for (int mt = 0; mt < MT; mt++)
        #pragma unroll
        for (int nt = 0; nt < NT; nt++)
            #pragma unroll
            for (int i = 0; i < 4; i++) acc[mt][nt][i] = 0.0f;

    const int g = lane >> 3, r = lane & 7;

    #pragma unroll 1
    for (int c = 0; c < CCH; c++) {
        asm volatile("cp.async.wait_group 1;" ::: "memory");
        __syncthreads();
        if (c + STAGES - 1 < CCH) issue(c + STAGES - 1, (c + STAGES - 1) % STAGES);
        asm volatile("cp.async.commit_group;" ::: "memory");  // uniform count

        const uint32_t sA  = sb + (uint32_t)(c % STAGES) * STAGE;
        const uint32_t sBm = sA + A_BYTES;

        // 4 k16 steps per 64-half chunk; byte addressing identical to the
        // previous tf32-as-b16 path (k16 step = 32 bytes, k8 tile = 16 bytes).
        #pragma unroll
        for (int ks = 0; ks < 4; ks++) {
            uint32_t bf[NT * 2];
            #pragma unroll
            for (int p = 0; p < NT / 2; p++) {
                int brow = wn * 64 + p * 16 + ((g >> 1) << 3) + r;
                int bcol = ks * 32 + ((g & 1) << 4);
                ldsm4(&bf[4 * p], sBm + sw128((uint32_t)(brow * 128 + bcol)));
            }
            uint32_t af[2][4];
            {
                int arow = wm * WM + ((g & 1) << 3) + r;
                int acol = ks * 32 + ((g >> 1) << 4);
                ldsm4(af[0], sA + sw128((uint32_t)(arow * 128 + acol)));
            }
            #pragma unroll
            for (int mt = 0; mt < MT; mt++) {
                if (mt + 1 < MT) {
                    int arow = wm * WM + (mt + 1) * 16 + ((g & 1) << 3) + r;
                    int acol = ks * 32 + ((g >> 1) << 4);
                    ldsm4(af[(mt + 1) & 1], sA + sw128((uint32_t)(arow * 128 + acol)));
                }
                #pragma unroll
                for (int nt = 0; nt < NT; nt++)
                    mma16(acc[mt][nt], af[mt & 1], bf[nt * 2], bf[nt * 2 + 1]);
            }
        }
    }

    // ---------------- epilogue ----------------
    const int qr = lane >> 2, rm = lane & 3;

    #pragma unroll
    for (int mt = 0; mt < MT; mt++) {
        const int lr0 = wm * WM + mt * 16 + qr;
        const int lr1 = lr0 + 8;
        float p0 = 1.0f, p1 = 1.0f;
        if (MODE == 0) {
            p0 = probs[s_token[lr0] * NEXP + e];
            p1 = probs[s_token[lr1] * NEXP + e];
        }
        #pragma unroll
        for (int nt = 0; nt < NT; nt++) {
            const int col = n0 + wn * 64 + nt * 8 + (rm << 1);
            if (MODE == 0) {
                __half2 h0 = __floats2half2_rn(gelu_exact(acc[mt][nt][0]) * p0,
                                               gelu_exact(acc[mt][nt][1]) * p0);
                __half2 h1 = __floats2half2_rn(gelu_exact(acc[mt][nt][2]) * p1,
                                               gelu_exact(acc[mt][nt][3]) * p1);
                *(__half2*)&CoutH[(size_t)(row_base + lr0) * FFN + col] = h0;
                *(__half2*)&CoutH[(size_t)(row_base + lr1) * FFN + col] = h1;
            } else {
                float2 v0, v1;
                v0.x = acc[mt][nt][0]; v0.y = acc[mt][nt][1];
                v1.x = acc[mt][nt][2]; v1.y = acc[mt][nt][3];
                *(float2*)&CoutF[(size_t)(row_base + lr0) * HID + col] = v0;
                *(float2*)&CoutF[(size_t)(row_base + lr1) * HID + col] = v1;
            }
        }
    }
}

// ---------------------------------------------------------------------------
// launch
// ---------------------------------------------------------------------------
extern "C" void kernel_launch(void* const* d_in, const int* in_sizes, int n_in,
                              void* d_out, int out_size) {
    const float* x     = (const float*)d_in[0];   // hidden_states [T,H]
    const float* resid = (const float*)d_in[1];   // mlp_residual  [T,H]
    const float* probs = (const float*)d_in[2];   // probs [T,E] (masked)
    // d_in[3] = routing_map (unused: probs>0 is the same mask, dtype-safe)
    const float* w1    = (const float*)d_in[4];   // [E,H,F]
    const float* w2    = (const float*)d_in[5];   // [E,F,H]
    float* out = (float*)d_out;

    __half *xr, *w1t, *w2t, *c1p;
    float *yp;
    int *idxp, *slotp, *cntp;
    cudaGetSymbolAddress((void**)&xr,   g_xr);
    cudaGetSymbolAddress((void**)&w1t,  g_w1t);
    cudaGetSymbolAddress((void**)&w2t,  g_w2t);
    cudaGetSymbolAddress((void**)&c1p,  g_c1p);
    cudaGetSymbolAddress((void**)&yp,   g_y);
    cudaGetSymbolAddress((void**)&idxp, g_idx);
    cudaGetSymbolAddress((void**)&slotp, g_slot);
    cudaGetSymbolAddress((void**)&cntp, g_cnt);

    // 64x128 CTA, 3-stage, occ 3: smem = 3*24576 + 256 = 73984 (x3 <= 228KB)
    constexpr int SMEM = 3 * (64 * 128 + 128 * 128) + 64 * 4;
    auto* k1 = moe_gemm<0>;
    auto* k2 = moe_gemm<1>;
    cudaFuncSetAttribute(k1, cudaFuncAttributeMaxDynamicSharedMemorySize, SMEM);
    cudaFuncSetAttribute(k2, cudaFuncAttributeMaxDynamicSharedMemorySize, SMEM);

    // merged prep + routing (cnt==0 at entry: static init / reset by combine)
    prep<<<10248, 256>>>(w1, w1t, w2, w2t, x, xr, probs, idxp, slotp, cntp);

    // routed GEMM1: gather X -> gelu*probs -> c1p(fp16). grid (33, 128)
    k1<<<dim3(TPE, NEXP * (FFN / 128)), 128, SMEM>>>(
        xr, w1t, probs, idxp, cntp, c1p, nullptr, HID);
    // routed GEMM2: c1p @ W2[e] -> y(fp32).            grid (8, 132)
    k2<<<dim3(HID / 128, NEXP * TPE), 128, SMEM>>>(
        c1p, w2t, probs, idxp, cntp, nullptr, yp, FFN);
    // combine: out = resid + sum_topk y; also resets cnt for next replay
    combine<<<T_TOK, 256>>>(yp, probs, slotp, resid, out, cntp);
}